// round 15
// baseline (speedup 1.0000x reference)
#include <cuda_runtime.h>
#include <cuda_fp16.h>
#include <math.h>
#include <stdint.h>

// Problem constants (fixed shapes per reference)
#define NN 50000
#define EE 800000
#define DD 256
#define CC 2
#define ETOT (EE + NN)   // edges + self loops = 850000
#define SLOPE 0.2f
#define SCB 196          // ceil(NN / 256) scan blocks

// ---------------- scratch (__device__ globals; device-code-only references) --
__device__ __half g_hA[(size_t)NN * DD];  // GEMM output h, fp16 (gather path only)
__device__ float  g_hB[(size_t)NN * DD];  // aggregated/relu'd layer output (fp32)
__device__ float  g_es[NN];
__device__ float  g_ed[NN];
__device__ int    g_deg[NN];
__device__ int    g_off[NN + 1];
__device__ int    g_cursor[NN];
__device__ int    g_csr_src[ETOT];
__device__ float  g_ex[ETOT];
__device__ int    g_part[256];            // scan partials (SCB used)
__device__ int    g_is64;                 // edge_index dtype flag

// ---------------- edge dtype probe ------------------------------------------
__global__ void k_detect(const int* __restrict__ ei) {
    int all0 = 1;
#pragma unroll
    for (int i = 1; i < 128; i += 2) all0 &= (ei[i] == 0);
    g_is64 = all0;
}

__device__ __forceinline__ int edge_src(const int* __restrict__ ei, int i) {
    return g_is64 ? ei[2 * i] : ei[i];
}
__device__ __forceinline__ int edge_dst(const int* __restrict__ ei, int i) {
    return g_is64 ? ei[2 * EE + 2 * i] : ei[EE + i];
}

// ---------------- CSR build ---------------------------------------------------
__global__ void k_init_deg() {
    int i = blockIdx.x * blockDim.x + threadIdx.x;
    if (i < NN) g_deg[i] = 1;   // self loop
}

__global__ void k_zero_attn() {
    int i = blockIdx.x * blockDim.x + threadIdx.x;
    if (i < NN) { g_es[i] = 0.f; g_ed[i] = 0.f; }
}

__global__ void k_hist(const int* __restrict__ ei) {
    int i = blockIdx.x * blockDim.x + threadIdx.x;
    if (i < EE) {
        int d = edge_dst(ei, i);
        if ((unsigned)d < NN) atomicAdd(&g_deg[d], 1);
    }
}

__global__ void k_scan1() {
    __shared__ int red[8];
    int i = blockIdx.x * 256 + threadIdx.x;
    int v = (i < NN) ? g_deg[i] : 0;
    int s = v;
#pragma unroll
    for (int o = 16; o; o >>= 1) s += __shfl_xor_sync(0xFFFFFFFFu, s, o);
    if ((threadIdx.x & 31) == 0) red[threadIdx.x >> 5] = s;
    __syncthreads();
    if (threadIdx.x < 8) {
        int t = red[threadIdx.x];
#pragma unroll
        for (int o = 4; o; o >>= 1) t += __shfl_xor_sync(0xFFu, t, o);
        if (threadIdx.x == 0) g_part[blockIdx.x] = t;
    }
}

__global__ void k_scan2() {
    __shared__ int sm[256];
    int t = threadIdx.x;
    int v = (t < SCB) ? g_part[t] : 0;
    sm[t] = v;
    __syncthreads();
#pragma unroll
    for (int off = 1; off < 256; off <<= 1) {
        int u = (t >= off) ? sm[t - off] : 0;
        __syncthreads();
        sm[t] += u;
        __syncthreads();
    }
    if (t < SCB) g_part[t] = sm[t] - v;
}

__global__ void k_scan3() {
    __shared__ int sm[256];
    int t = threadIdx.x;
    int i = blockIdx.x * 256 + t;
    int v = (i < NN) ? g_deg[i] : 0;
    sm[t] = v;
    __syncthreads();
#pragma unroll
    for (int off = 1; off < 256; off <<= 1) {
        int u = (t >= off) ? sm[t - off] : 0;
        __syncthreads();
        sm[t] += u;
        __syncthreads();
    }
    int excl = sm[t] - v + g_part[blockIdx.x];
    if (i < NN) { g_off[i] = excl; g_cursor[i] = excl; }
    if (i == NN - 1) g_off[NN] = excl + v;
}

__global__ void k_fill(const int* __restrict__ ei) {
    int i = blockIdx.x * blockDim.x + threadIdx.x;
    if (i >= ETOT) return;
    int s, d;
    if (i < EE) {
        s = edge_src(ei, i);
        d = edge_dst(ei, i);
        if ((unsigned)s >= NN || (unsigned)d >= NN) return;
    } else {
        s = d = i - EE;
    }
    int pos = atomicAdd(&g_cursor[d], 1);
    if ((unsigned)pos < ETOT) g_csr_src[pos] = s;
}

// ---------------- TF32 helpers -------------------------------------------------
__device__ __forceinline__ uint32_t f2tf32(float x) {
    uint32_t r;
    asm("cvt.rna.tf32.f32 %0, %1;" : "=r"(r) : "f"(x));
    return r;
}

__device__ __forceinline__ void mma1688(float* c, const uint32_t* a, const uint32_t* b) {
    asm volatile(
        "mma.sync.aligned.m16n8k8.row.col.f32.tf32.tf32.f32 "
        "{%0,%1,%2,%3}, {%4,%5,%6,%7}, {%8,%9}, {%0,%1,%2,%3};\n"
        : "+f"(c[0]), "+f"(c[1]), "+f"(c[2]), "+f"(c[3])
        : "r"(a[0]), "r"(a[1]), "r"(a[2]), "r"(a[3]), "r"(b[0]), "r"(b[1]));
}

// ---------------- TF32 GEMM (3xTF32) + fused attention dots --------------------
// g_hA(fp16) = A @ W ; g_es += h.a_s ; g_ed += h.a_d    (dots at fp32)
// 128x128 CTA tile, BK=16, 8 warps (2m x 4n), warp tile 64x32, m16n8k8.
__global__ void __launch_bounds__(256)
k_gemm(const float* Aext, const float* __restrict__ B, int M,
       const float* __restrict__ a_s, const float* __restrict__ a_d) {
    const float* A = Aext ? Aext : (const float*)g_hB;
    __half* Cout = g_hA;
    const int K = 256, NC = 256;

    __shared__ uint32_t Ah[16][132], Al[16][132];
    __shared__ uint32_t Bh[16][132], Bl[16][132];

    const int tid  = threadIdx.x;
    const int wid  = tid >> 5;
    const int lane = tid & 31;
    const int gid  = lane >> 2;      // 0..7
    const int tig  = lane & 3;       // 0..3
    const int wm   = wid >> 2;       // 0..1
    const int wn   = wid & 3;        // 0..3
    const int brow = blockIdx.x * 128;
    const int bcol = blockIdx.y * 128;

    const int a_row = tid >> 1;          // 0..127
    const int a_k   = (tid & 1) * 8;     // 0 or 8
    const int b_row = tid >> 4;          // 0..15 (k)
    const int b_col = (tid & 15) * 8;    // 0..120 (n)
    const int gr    = brow + a_row;

    float acc[4][4][4];
#pragma unroll
    for (int mf = 0; mf < 4; mf++)
#pragma unroll
        for (int nf = 0; nf < 4; nf++)
#pragma unroll
            for (int c = 0; c < 4; c++) acc[mf][nf][c] = 0.f;

    float sa[8], sb[8];
    // prologue: load tile k0=0, convert, store
    {
        float4 av0 = make_float4(0.f, 0.f, 0.f, 0.f), av1 = av0;
        if (gr < M) {
            av0 = *(const float4*)&A[(size_t)gr * K + a_k];
            av1 = *(const float4*)&A[(size_t)gr * K + a_k + 4];
        }
        float4 bv0 = *(const float4*)&B[(size_t)b_row * NC + bcol + b_col];
        float4 bv1 = *(const float4*)&B[(size_t)b_row * NC + bcol + b_col + 4];
        sa[0]=av0.x; sa[1]=av0.y; sa[2]=av0.z; sa[3]=av0.w;
        sa[4]=av1.x; sa[5]=av1.y; sa[6]=av1.z; sa[7]=av1.w;
        sb[0]=bv0.x; sb[1]=bv0.y; sb[2]=bv0.z; sb[3]=bv0.w;
        sb[4]=bv1.x; sb[5]=bv1.y; sb[6]=bv1.z; sb[7]=bv1.w;
#pragma unroll
        for (int i = 0; i < 8; i++) {
            uint32_t h = f2tf32(sa[i]);
            Ah[a_k + i][a_row] = h;
            Al[a_k + i][a_row] = f2tf32(sa[i] - __uint_as_float(h));
            uint32_t hb = f2tf32(sb[i]);
            Bh[b_row][b_col + i] = hb;
            Bl[b_row][b_col + i] = f2tf32(sb[i] - __uint_as_float(hb));
        }
    }
    __syncthreads();

    for (int k0 = 16; k0 <= K; k0 += 16) {
        const bool more = (k0 < K);
        if (more) {   // prefetch next tile into registers
            float4 av0 = make_float4(0.f, 0.f, 0.f, 0.f), av1 = av0;
            if (gr < M) {
                av0 = *(const float4*)&A[(size_t)gr * K + k0 + a_k];
                av1 = *(const float4*)&A[(size_t)gr * K + k0 + a_k + 4];
            }
            float4 bv0 = *(const float4*)&B[(size_t)(k0 + b_row) * NC + bcol + b_col];
            float4 bv1 = *(const float4*)&B[(size_t)(k0 + b_row) * NC + bcol + b_col + 4];
            sa[0]=av0.x; sa[1]=av0.y; sa[2]=av0.z; sa[3]=av0.w;
            sa[4]=av1.x; sa[5]=av1.y; sa[6]=av1.z; sa[7]=av1.w;
            sb[0]=bv0.x; sb[1]=bv0.y; sb[2]=bv0.z; sb[3]=bv0.w;
            sb[4]=bv1.x; sb[5]=bv1.y; sb[6]=bv1.z; sb[7]=bv1.w;
        }

#pragma unroll
        for (int kc = 0; kc < 2; kc++) {
            const int kb = kc * 8;
            uint32_t ah[4][4], al[4][4], bh[4][2], bl[4][2];
#pragma unroll
            for (int mf = 0; mf < 4; mf++) {
                int m0 = wm * 64 + mf * 16 + gid;
                ah[mf][0] = Ah[kb + tig][m0];
                ah[mf][1] = Ah[kb + tig][m0 + 8];
                ah[mf][2] = Ah[kb + tig + 4][m0];
                ah[mf][3] = Ah[kb + tig + 4][m0 + 8];
                al[mf][0] = Al[kb + tig][m0];
                al[mf][1] = Al[kb + tig][m0 + 8];
                al[mf][2] = Al[kb + tig + 4][m0];
                al[mf][3] = Al[kb + tig + 4][m0 + 8];
            }
#pragma unroll
            for (int nf = 0; nf < 4; nf++) {
                int n0 = wn * 32 + nf * 8 + gid;
                bh[nf][0] = Bh[kb + tig][n0];
                bh[nf][1] = Bh[kb + tig + 4][n0];
                bl[nf][0] = Bl[kb + tig][n0];
                bl[nf][1] = Bl[kb + tig + 4][n0];
            }
#pragma unroll
            for (int mf = 0; mf < 4; mf++)
#pragma unroll
                for (int nf = 0; nf < 4; nf++) {
                    mma1688(acc[mf][nf], ah[mf], bh[nf]);
                    mma1688(acc[mf][nf], ah[mf], bl[nf]);
                    mma1688(acc[mf][nf], al[mf], bh[nf]);
                }
        }

        if (more) {
            __syncthreads();   // all fragment reads of current tile done
#pragma unroll
            for (int i = 0; i < 8; i++) {
                uint32_t h = f2tf32(sa[i]);
                Ah[a_k + i][a_row] = h;
                Al[a_k + i][a_row] = f2tf32(sa[i] - __uint_as_float(h));
                uint32_t hb = f2tf32(sb[i]);
                Bh[b_row][b_col + i] = hb;
                Bl[b_row][b_col + i] = f2tf32(sb[i] - __uint_as_float(hb));
            }
            __syncthreads();
        }
    }

    // epilogue: fused attention dots (fp32) + fp16 C store
    float as0[4], as1[4], ad0[4], ad1[4];
#pragma unroll
    for (int nf = 0; nf < 4; nf++) {
        int c = bcol + wn * 32 + nf * 8 + 2 * tig;
        as0[nf] = a_s[c];     as1[nf] = a_s[c + 1];
        ad0[nf] = a_d[c];     ad1[nf] = a_d[c + 1];
    }
#pragma unroll
    for (int mf = 0; mf < 4; mf++) {
        int r0 = brow + wm * 64 + mf * 16 + gid;
        int r1 = r0 + 8;
        float ps0 = 0.f, pd0 = 0.f, ps1 = 0.f, pd1 = 0.f;
#pragma unroll
        for (int nf = 0; nf < 4; nf++) {
            ps0 = fmaf(acc[mf][nf][0], as0[nf], fmaf(acc[mf][nf][1], as1[nf], ps0));
            pd0 = fmaf(acc[mf][nf][0], ad0[nf], fmaf(acc[mf][nf][1], ad1[nf], pd0));
            ps1 = fmaf(acc[mf][nf][2], as0[nf], fmaf(acc[mf][nf][3], as1[nf], ps1));
            pd1 = fmaf(acc[mf][nf][2], ad0[nf], fmaf(acc[mf][nf][3], ad1[nf], pd1));
        }
#pragma unroll
        for (int o = 1; o <= 2; o <<= 1) {
            ps0 += __shfl_xor_sync(0xFFFFFFFFu, ps0, o);
            pd0 += __shfl_xor_sync(0xFFFFFFFFu, pd0, o);
            ps1 += __shfl_xor_sync(0xFFFFFFFFu, ps1, o);
            pd1 += __shfl_xor_sync(0xFFFFFFFFu, pd1, o);
        }
#pragma unroll
        for (int nf = 0; nf < 4; nf++) {
            int c = bcol + wn * 32 + nf * 8 + 2 * tig;
            if (r0 < M)
                ((__half2*)Cout)[((size_t)r0 * NC + c) >> 1] =
                    __floats2half2_rn(acc[mf][nf][0], acc[mf][nf][1]);
            if (r1 < M)
                ((__half2*)Cout)[((size_t)r1 * NC + c) >> 1] =
                    __floats2half2_rn(acc[mf][nf][2], acc[mf][nf][3]);
        }
        if (tig == 0) {
            if (r0 < M) { atomicAdd(&g_es[r0], ps0); atomicAdd(&g_ed[r0], pd0); }
            if (r1 < M) { atomicAdd(&g_es[r1], ps1); atomicAdd(&g_ed[r1], pd1); }
        }
    }
}

// ---------------- aggregation: online segment softmax + fp16 gather -------------
// 128 threads per block; thread t owns the half2 feature pair (2t, 2t+1).
// If Wc != nullptr: fused classifier + log_softmax.
__global__ void __launch_bounds__(128)
k_aggr(const float* __restrict__ bias,
       const float* __restrict__ Wc, const float* __restrict__ bc,
       float* __restrict__ cls_out) {
    const __half2* Hin = (const __half2*)g_hA;
    const int node = blockIdx.x;
    const int tid = threadIdx.x;      // 0..127
    const int lane = tid & 31;
    const int beg = g_off[node];
    const int end = g_off[node + 1];
    const float edv = g_ed[node];

    __shared__ float redm[4], redd[4];
    __shared__ float s_m, s_inv;
    __shared__ int   s_src[128];
    __shared__ float s_w[128];

    // pass A: online softmax (max + denominator in one sweep); store raw e
    float m = -1e30f, d = 0.f;
    for (int j = beg + tid; j < end; j += 128) {
        float e = g_es[g_csr_src[j]] + edv;
        e = (e > 0.f) ? e : SLOPE * e;
        g_ex[j] = e;
        if (e > m) { d = fmaf(d, __expf(m - e), 1.f); m = e; }
        else       { d += __expf(e - m); }
    }
#pragma unroll
    for (int o = 16; o; o >>= 1) {
        float om = __shfl_xor_sync(0xFFFFFFFFu, m, o);
        float od = __shfl_xor_sync(0xFFFFFFFFu, d, o);
        float nm = fmaxf(m, om);
        d = d * __expf(m - nm) + od * __expf(om - nm);
        m = nm;
    }
    if (lane == 0) { redm[tid >> 5] = m; redd[tid >> 5] = d; }
    __syncthreads();
    if (tid < 4) {
        float vm = redm[tid], vd = redd[tid];
#pragma unroll
        for (int o = 2; o; o >>= 1) {
            float om = __shfl_xor_sync(0xFu, vm, o);
            float od = __shfl_xor_sync(0xFu, vd, o);
            float nm = fmaxf(vm, om);
            vd = vd * __expf(vm - nm) + od * __expf(om - nm);
            vm = nm;
        }
        if (tid == 0) { s_m = vm; s_inv = 1.f / vd; }
    }
    __syncthreads();
    const float mm  = s_m;
    const float inv = s_inv;

    // pass C: weighted fp16 gather (thread = one half2 feature pair)
    float ax = 0.f, ay = 0.f;
    for (int base = beg; base < end; base += 128) {
        int n = min(128, end - base);
        __syncthreads();
        if (tid < n) {
            s_src[tid] = g_csr_src[base + tid];
            s_w[tid]   = __expf(g_ex[base + tid] - mm);
        }
        __syncthreads();
        for (int k = 0; k < n; k++) {
            float w = s_w[k];
            float2 f = __half22float2(Hin[(size_t)s_src[k] * 128 + tid]);
            ax = fmaf(w, f.x, ax);
            ay = fmaf(w, f.y, ay);
        }
    }
    float v0 = fmaxf(fmaf(ax, inv, bias[2 * tid]), 0.f);
    float v1 = fmaxf(fmaf(ay, inv, bias[2 * tid + 1]), 0.f);

    if (Wc == nullptr) {
        ((float2*)g_hB)[(size_t)node * 128 + tid] = make_float2(v0, v1);
        return;
    }

    // fused classifier + log_softmax (Wc is [256,2] row-major)
    float p0 = v0 * Wc[4 * tid + 0] + v1 * Wc[4 * tid + 2];
    float p1 = v0 * Wc[4 * tid + 1] + v1 * Wc[4 * tid + 3];
#pragma unroll
    for (int o = 16; o; o >>= 1) {
        p0 += __shfl_xor_sync(0xFFFFFFFFu, p0, o);
        p1 += __shfl_xor_sync(0xFFFFFFFFu, p1, o);
    }
    __syncthreads();   // red arrays reused
    if (lane == 0) { redm[tid >> 5] = p0; redd[tid >> 5] = p1; }
    __syncthreads();
    if (tid < 4) {
        float l0 = redm[tid], l1 = redd[tid];
#pragma unroll
        for (int o = 2; o; o >>= 1) {
            l0 += __shfl_xor_sync(0xFu, l0, o);
            l1 += __shfl_xor_sync(0xFu, l1, o);
        }
        if (tid == 0) {
            l0 += bc[0]; l1 += bc[1];
            float mx = fmaxf(l0, l1);
            float z0 = l0 - mx, z1 = l1 - mx;
            float lse = logf(expf(z0) + expf(z1));
            cls_out[(size_t)node * 2 + 0] = z0 - lse;
            cls_out[(size_t)node * 2 + 1] = z1 - lse;
        }
    }
}

// ---------------- launch ---------------------------------------------------------
extern "C" void kernel_launch(void* const* d_in, const int* in_sizes, int n_in,
                              void* d_out, int out_size) {
    const float* x   = (const float*)d_in[0];
    const int*   ei  = (const int*)d_in[1];    // int32 OR int64 (device-probed)
    const float* W1  = (const float*)d_in[2];
    const float* a1s = (const float*)d_in[3];
    const float* a1d = (const float*)d_in[4];
    const float* b1  = (const float*)d_in[5];
    const float* W2  = (const float*)d_in[6];
    const float* a2s = (const float*)d_in[7];
    const float* a2d = (const float*)d_in[8];
    const float* b2  = (const float*)d_in[9];
    const float* Wc  = (const float*)d_in[10];
    const float* bc  = (const float*)d_in[11];
    float*       out = (float*)d_out;

    // CSR build
    k_detect<<<1, 1>>>(ei);
    k_init_deg<<<SCB, 256>>>();
    k_hist<<<(EE + 255) / 256, 256>>>(ei);
    k_scan1<<<SCB, 256>>>();
    k_scan2<<<1, 256>>>();
    k_scan3<<<SCB, 256>>>();
    k_fill<<<(ETOT + 255) / 256, 256>>>(ei);

    dim3 ggrid((NN + 127) / 128, DD / 128);   // 391 x 2

    // layer 1
    k_zero_attn<<<SCB, 256>>>();
    k_gemm<<<ggrid, 256>>>(x, W1, NN, a1s, a1d);
    k_aggr<<<NN, 128>>>(b1, nullptr, nullptr, nullptr);

    // layer 2 (+ fused classifier)
    k_zero_attn<<<SCB, 256>>>();
    k_gemm<<<ggrid, 256>>>(nullptr, W2, NN, a2s, a2d);
    k_aggr<<<NN, 128>>>(b2, Wc, bc, out);
}

// round 16
// speedup vs baseline: 1.3813x; 1.3813x over previous
#include <cuda_runtime.h>
#include <cuda_fp16.h>
#include <math.h>
#include <stdint.h>

// Problem constants (fixed shapes per reference)
#define NN 50000
#define EE 800000
#define DD 256
#define CC 2
#define ETOT (EE + NN)   // edges + self loops = 850000
#define SLOPE 0.2f
#define SCB 196          // ceil(NN / 256) scan blocks

// ---------------- scratch (__device__ globals; device-code-only references) --
__device__ __half g_hA[(size_t)NN * DD];  // GEMM output h, fp16 (gather path only)
__device__ float  g_hB[(size_t)NN * DD];  // aggregated/relu'd layer output (fp32)
__device__ float  g_es[NN];
__device__ float  g_ed[NN];
__device__ int    g_deg[NN];
__device__ int    g_off[NN + 1];
__device__ int    g_cursor[NN];
__device__ int    g_csr_src[ETOT];
__device__ float  g_ex[ETOT];
__device__ int    g_part[256];            // scan partials (SCB used)
__device__ int    g_is64;                 // edge_index dtype flag

// ---------------- edge dtype probe ------------------------------------------
__global__ void k_detect(const int* __restrict__ ei) {
    int all0 = 1;
#pragma unroll
    for (int i = 1; i < 128; i += 2) all0 &= (ei[i] == 0);
    g_is64 = all0;
}

__device__ __forceinline__ int edge_src(const int* __restrict__ ei, int i) {
    return g_is64 ? ei[2 * i] : ei[i];
}
__device__ __forceinline__ int edge_dst(const int* __restrict__ ei, int i) {
    return g_is64 ? ei[2 * EE + 2 * i] : ei[EE + i];
}

// ---------------- CSR build ---------------------------------------------------
__global__ void k_init_deg() {
    int i = blockIdx.x * blockDim.x + threadIdx.x;
    if (i < NN) g_deg[i] = 1;   // self loop
}

__global__ void k_zero_attn() {
    int i = blockIdx.x * blockDim.x + threadIdx.x;
    if (i < NN) { g_es[i] = 0.f; g_ed[i] = 0.f; }
}

__global__ void k_hist(const int* __restrict__ ei) {
    int i = blockIdx.x * blockDim.x + threadIdx.x;
    if (i < EE) {
        int d = edge_dst(ei, i);
        if ((unsigned)d < NN) atomicAdd(&g_deg[d], 1);
    }
}

__global__ void k_scan1() {
    __shared__ int red[8];
    int i = blockIdx.x * 256 + threadIdx.x;
    int v = (i < NN) ? g_deg[i] : 0;
    int s = v;
#pragma unroll
    for (int o = 16; o; o >>= 1) s += __shfl_xor_sync(0xFFFFFFFFu, s, o);
    if ((threadIdx.x & 31) == 0) red[threadIdx.x >> 5] = s;
    __syncthreads();
    if (threadIdx.x < 8) {
        int t = red[threadIdx.x];
#pragma unroll
        for (int o = 4; o; o >>= 1) t += __shfl_xor_sync(0xFFu, t, o);
        if (threadIdx.x == 0) g_part[blockIdx.x] = t;
    }
}

__global__ void k_scan2() {
    __shared__ int sm[256];
    int t = threadIdx.x;
    int v = (t < SCB) ? g_part[t] : 0;
    sm[t] = v;
    __syncthreads();
#pragma unroll
    for (int off = 1; off < 256; off <<= 1) {
        int u = (t >= off) ? sm[t - off] : 0;
        __syncthreads();
        sm[t] += u;
        __syncthreads();
    }
    if (t < SCB) g_part[t] = sm[t] - v;
}

__global__ void k_scan3() {
    __shared__ int sm[256];
    int t = threadIdx.x;
    int i = blockIdx.x * 256 + t;
    int v = (i < NN) ? g_deg[i] : 0;
    sm[t] = v;
    __syncthreads();
#pragma unroll
    for (int off = 1; off < 256; off <<= 1) {
        int u = (t >= off) ? sm[t - off] : 0;
        __syncthreads();
        sm[t] += u;
        __syncthreads();
    }
    int excl = sm[t] - v + g_part[blockIdx.x];
    if (i < NN) { g_off[i] = excl; g_cursor[i] = excl; }
    if (i == NN - 1) g_off[NN] = excl + v;
}

__global__ void k_fill(const int* __restrict__ ei) {
    int i = blockIdx.x * blockDim.x + threadIdx.x;
    if (i >= ETOT) return;
    int s, d;
    if (i < EE) {
        s = edge_src(ei, i);
        d = edge_dst(ei, i);
        if ((unsigned)s >= NN || (unsigned)d >= NN) return;
    } else {
        s = d = i - EE;
    }
    int pos = atomicAdd(&g_cursor[d], 1);
    if ((unsigned)pos < ETOT) g_csr_src[pos] = s;
}

// ---------------- fp16 split helpers -------------------------------------------
__device__ __forceinline__ void fsplit(float x, __half& h, __half& l) {
    h = __float2half_rn(x);
    l = __float2half_rn(x - __half2float(h));
}

__device__ __forceinline__ void mma16816(float* c, const uint32_t* a, const uint32_t* b) {
    asm volatile(
        "mma.sync.aligned.m16n8k16.row.col.f32.f16.f16.f32 "
        "{%0,%1,%2,%3}, {%4,%5,%6,%7}, {%8,%9}, {%0,%1,%2,%3};\n"
        : "+f"(c[0]), "+f"(c[1]), "+f"(c[2]), "+f"(c[3])
        : "r"(a[0]), "r"(a[1]), "r"(a[2]), "r"(a[3]), "r"(b[0]), "r"(b[1]));
}

// ---------------- split-fp16 GEMM (3-term) + fused attention dots ---------------
// g_hA(fp16) = A @ W ; g_es += h.a_s ; g_ed += h.a_d    (dots at fp32)
// 128x128 CTA tile, BK=16, 8 warps (2m x 4n), warp tile 64x32, mma.m16n8k16.
// A smem [m][k] (24-half stride); B smem transposed [n][k] (26-half stride).
__global__ void __launch_bounds__(256)
k_gemm(const float* Aext, const float* __restrict__ B, int M,
       const float* __restrict__ a_s, const float* __restrict__ a_d) {
    const float* A = Aext ? Aext : (const float*)g_hB;
    __half* Cout = g_hA;
    const int K = 256, NC = 256;

    __shared__ __half Ash[128][24], Asl[128][24];   // [m][k]
    __shared__ __half Bsh[128][26], Bsl[128][26];   // [n][k]

    const int tid  = threadIdx.x;
    const int wid  = tid >> 5;
    const int lane = tid & 31;
    const int gid  = lane >> 2;      // 0..7
    const int tig  = lane & 3;       // 0..3
    const int wm   = wid >> 2;       // 0..1
    const int wn   = wid & 3;        // 0..3
    const int brow = blockIdx.x * 128;
    const int bcol = blockIdx.y * 128;

    // A global->smem mapping: thread = (1 row, 8 k)
    const int a_row = tid >> 1;          // 0..127
    const int a_k   = (tid & 1) * 8;     // 0 or 8
    const int gr    = brow + a_row;
    // B global->smem mapping: thread = (2 consecutive k rows, 4 n)
    const int b_kp  = tid >> 5;          // 0..7  (k pair index; k = 2*b_kp)
    const int b_n   = (tid & 31) * 4;    // 0..124 local n

    float acc[4][4][4];
#pragma unroll
    for (int mf = 0; mf < 4; mf++)
#pragma unroll
        for (int nf = 0; nf < 4; nf++)
#pragma unroll
            for (int c = 0; c < 4; c++) acc[mf][nf][c] = 0.f;

    float sa[8], sb0[4], sb1[4];

    // prologue: load + split + store tile k0=0
    {
        float4 av0 = make_float4(0.f, 0.f, 0.f, 0.f), av1 = av0;
        if (gr < M) {
            av0 = *(const float4*)&A[(size_t)gr * K + a_k];
            av1 = *(const float4*)&A[(size_t)gr * K + a_k + 4];
        }
        sa[0]=av0.x; sa[1]=av0.y; sa[2]=av0.z; sa[3]=av0.w;
        sa[4]=av1.x; sa[5]=av1.y; sa[6]=av1.z; sa[7]=av1.w;
        float4 bv0 = *(const float4*)&B[(size_t)(2 * b_kp) * NC + bcol + b_n];
        float4 bv1 = *(const float4*)&B[(size_t)(2 * b_kp + 1) * NC + bcol + b_n];
        sb0[0]=bv0.x; sb0[1]=bv0.y; sb0[2]=bv0.z; sb0[3]=bv0.w;
        sb1[0]=bv1.x; sb1[1]=bv1.y; sb1[2]=bv1.z; sb1[3]=bv1.w;
#pragma unroll
        for (int i = 0; i < 8; i++) {
            __half h, l;
            fsplit(sa[i], h, l);
            Ash[a_row][a_k + i] = h;
            Asl[a_row][a_k + i] = l;
        }
#pragma unroll
        for (int i = 0; i < 4; i++) {
            __half h0, l0, h1, l1;
            fsplit(sb0[i], h0, l0);
            fsplit(sb1[i], h1, l1);
            *(half2*)&Bsh[b_n + i][2 * b_kp] = __halves2half2(h0, h1);
            *(half2*)&Bsl[b_n + i][2 * b_kp] = __halves2half2(l0, l1);
        }
    }
    __syncthreads();

    for (int k0 = 16; k0 <= K; k0 += 16) {
        const bool more = (k0 < K);
        if (more) {   // prefetch next tile into registers (hidden by 48 MMAs/warp)
            float4 av0 = make_float4(0.f, 0.f, 0.f, 0.f), av1 = av0;
            if (gr < M) {
                av0 = *(const float4*)&A[(size_t)gr * K + k0 + a_k];
                av1 = *(const float4*)&A[(size_t)gr * K + k0 + a_k + 4];
            }
            sa[0]=av0.x; sa[1]=av0.y; sa[2]=av0.z; sa[3]=av0.w;
            sa[4]=av1.x; sa[5]=av1.y; sa[6]=av1.z; sa[7]=av1.w;
            float4 bv0 = *(const float4*)&B[(size_t)(k0 + 2 * b_kp) * NC + bcol + b_n];
            float4 bv1 = *(const float4*)&B[(size_t)(k0 + 2 * b_kp + 1) * NC + bcol + b_n];
            sb0[0]=bv0.x; sb0[1]=bv0.y; sb0[2]=bv0.z; sb0[3]=bv0.w;
            sb1[0]=bv1.x; sb1[1]=bv1.y; sb1[2]=bv1.z; sb1[3]=bv1.w;
        }

        // fragment loads (m16n8k16 layout)
        uint32_t ah[4][4], al[4][4], bh[4][2], bl[4][2];
#pragma unroll
        for (int mf = 0; mf < 4; mf++) {
            int m0 = wm * 64 + mf * 16 + gid;
            ah[mf][0] = *(const uint32_t*)&Ash[m0][2 * tig];
            ah[mf][1] = *(const uint32_t*)&Ash[m0 + 8][2 * tig];
            ah[mf][2] = *(const uint32_t*)&Ash[m0][2 * tig + 8];
            ah[mf][3] = *(const uint32_t*)&Ash[m0 + 8][2 * tig + 8];
            al[mf][0] = *(const uint32_t*)&Asl[m0][2 * tig];
            al[mf][1] = *(const uint32_t*)&Asl[m0 + 8][2 * tig];
            al[mf][2] = *(const uint32_t*)&Asl[m0][2 * tig + 8];
            al[mf][3] = *(const uint32_t*)&Asl[m0 + 8][2 * tig + 8];
        }
#pragma unroll
        for (int nf = 0; nf < 4; nf++) {
            int n0 = wn * 32 + nf * 8 + gid;
            bh[nf][0] = *(const uint32_t*)&Bsh[n0][2 * tig];
            bh[nf][1] = *(const uint32_t*)&Bsh[n0][2 * tig + 8];
            bl[nf][0] = *(const uint32_t*)&Bsl[n0][2 * tig];
            bl[nf][1] = *(const uint32_t*)&Bsl[n0][2 * tig + 8];
        }

        // 3-term split-fp16: D += Ah*Bh + Ah*Bl + Al*Bh
#pragma unroll
        for (int mf = 0; mf < 4; mf++)
#pragma unroll
            for (int nf = 0; nf < 4; nf++) {
                mma16816(acc[mf][nf], ah[mf], bh[nf]);
                mma16816(acc[mf][nf], ah[mf], bl[nf]);
                mma16816(acc[mf][nf], al[mf], bh[nf]);
            }

        if (more) {
            __syncthreads();   // fragment reads of current tile done
#pragma unroll
            for (int i = 0; i < 8; i++) {
                __half h, l;
                fsplit(sa[i], h, l);
                Ash[a_row][a_k + i] = h;
                Asl[a_row][a_k + i] = l;
            }
#pragma unroll
            for (int i = 0; i < 4; i++) {
                __half h0, l0, h1, l1;
                fsplit(sb0[i], h0, l0);
                fsplit(sb1[i], h1, l1);
                *(half2*)&Bsh[b_n + i][2 * b_kp] = __halves2half2(h0, h1);
                *(half2*)&Bsl[b_n + i][2 * b_kp] = __halves2half2(l0, l1);
            }
            __syncthreads();
        }
    }

    // epilogue: fused attention dots (fp32) + fp16 C store (layout unchanged)
    float as0[4], as1[4], ad0[4], ad1[4];
#pragma unroll
    for (int nf = 0; nf < 4; nf++) {
        int c = bcol + wn * 32 + nf * 8 + 2 * tig;
        as0[nf] = a_s[c];     as1[nf] = a_s[c + 1];
        ad0[nf] = a_d[c];     ad1[nf] = a_d[c + 1];
    }
#pragma unroll
    for (int mf = 0; mf < 4; mf++) {
        int r0 = brow + wm * 64 + mf * 16 + gid;
        int r1 = r0 + 8;
        float ps0 = 0.f, pd0 = 0.f, ps1 = 0.f, pd1 = 0.f;
#pragma unroll
        for (int nf = 0; nf < 4; nf++) {
            ps0 = fmaf(acc[mf][nf][0], as0[nf], fmaf(acc[mf][nf][1], as1[nf], ps0));
            pd0 = fmaf(acc[mf][nf][0], ad0[nf], fmaf(acc[mf][nf][1], ad1[nf], pd0));
            ps1 = fmaf(acc[mf][nf][2], as0[nf], fmaf(acc[mf][nf][3], as1[nf], ps1));
            pd1 = fmaf(acc[mf][nf][2], ad0[nf], fmaf(acc[mf][nf][3], ad1[nf], pd1));
        }
#pragma unroll
        for (int o = 1; o <= 2; o <<= 1) {
            ps0 += __shfl_xor_sync(0xFFFFFFFFu, ps0, o);
            pd0 += __shfl_xor_sync(0xFFFFFFFFu, pd0, o);
            ps1 += __shfl_xor_sync(0xFFFFFFFFu, ps1, o);
            pd1 += __shfl_xor_sync(0xFFFFFFFFu, pd1, o);
        }
#pragma unroll
        for (int nf = 0; nf < 4; nf++) {
            int c = bcol + wn * 32 + nf * 8 + 2 * tig;
            if (r0 < M)
                ((__half2*)Cout)[((size_t)r0 * NC + c) >> 1] =
                    __floats2half2_rn(acc[mf][nf][0], acc[mf][nf][1]);
            if (r1 < M)
                ((__half2*)Cout)[((size_t)r1 * NC + c) >> 1] =
                    __floats2half2_rn(acc[mf][nf][2], acc[mf][nf][3]);
        }
        if (tig == 0) {
            if (r0 < M) { atomicAdd(&g_es[r0], ps0); atomicAdd(&g_ed[r0], pd0); }
            if (r1 < M) { atomicAdd(&g_es[r1], ps1); atomicAdd(&g_ed[r1], pd1); }
        }
    }
}

// ---------------- aggregation: online segment softmax + fp16 gather -------------
// 128 threads per block; thread t owns the half2 feature pair (2t, 2t+1).
// If Wc != nullptr: fused classifier + log_softmax.
__global__ void __launch_bounds__(128)
k_aggr(const float* __restrict__ bias,
       const float* __restrict__ Wc, const float* __restrict__ bc,
       float* __restrict__ cls_out) {
    const __half2* Hin = (const __half2*)g_hA;
    const int node = blockIdx.x;
    const int tid = threadIdx.x;      // 0..127
    const int lane = tid & 31;
    const int beg = g_off[node];
    const int end = g_off[node + 1];
    const float edv = g_ed[node];

    __shared__ float redm[4], redd[4];
    __shared__ float s_m, s_inv;
    __shared__ int   s_src[128];
    __shared__ float s_w[128];

    // pass A: online softmax (max + denominator in one sweep); store raw e
    float m = -1e30f, d = 0.f;
    for (int j = beg + tid; j < end; j += 128) {
        float e = g_es[g_csr_src[j]] + edv;
        e = (e > 0.f) ? e : SLOPE * e;
        g_ex[j] = e;
        if (e > m) { d = fmaf(d, __expf(m - e), 1.f); m = e; }
        else       { d += __expf(e - m); }
    }
#pragma unroll
    for (int o = 16; o; o >>= 1) {
        float om = __shfl_xor_sync(0xFFFFFFFFu, m, o);
        float od = __shfl_xor_sync(0xFFFFFFFFu, d, o);
        float nm = fmaxf(m, om);
        d = d * __expf(m - nm) + od * __expf(om - nm);
        m = nm;
    }
    if (lane == 0) { redm[tid >> 5] = m; redd[tid >> 5] = d; }
    __syncthreads();
    if (tid < 4) {
        float vm = redm[tid], vd = redd[tid];
#pragma unroll
        for (int o = 2; o; o >>= 1) {
            float om = __shfl_xor_sync(0xFu, vm, o);
            float od = __shfl_xor_sync(0xFu, vd, o);
            float nm = fmaxf(vm, om);
            vd = vd * __expf(vm - nm) + od * __expf(om - nm);
            vm = nm;
        }
        if (tid == 0) { s_m = vm; s_inv = 1.f / vd; }
    }
    __syncthreads();
    const float mm  = s_m;
    const float inv = s_inv;

    // pass C: weighted fp16 gather (thread = one half2 feature pair)
    float ax = 0.f, ay = 0.f;
    for (int base = beg; base < end; base += 128) {
        int n = min(128, end - base);
        __syncthreads();
        if (tid < n) {
            s_src[tid] = g_csr_src[base + tid];
            s_w[tid]   = __expf(g_ex[base + tid] - mm);
        }
        __syncthreads();
        for (int k = 0; k < n; k++) {
            float w = s_w[k];
            float2 f = __half22float2(Hin[(size_t)s_src[k] * 128 + tid]);
            ax = fmaf(w, f.x, ax);
            ay = fmaf(w, f.y, ay);
        }
    }
    float v0 = fmaxf(fmaf(ax, inv, bias[2 * tid]), 0.f);
    float v1 = fmaxf(fmaf(ay, inv, bias[2 * tid + 1]), 0.f);

    if (Wc == nullptr) {
        ((float2*)g_hB)[(size_t)node * 128 + tid] = make_float2(v0, v1);
        return;
    }

    // fused classifier + log_softmax (Wc is [256,2] row-major)
    float p0 = v0 * Wc[4 * tid + 0] + v1 * Wc[4 * tid + 2];
    float p1 = v0 * Wc[4 * tid + 1] + v1 * Wc[4 * tid + 3];
#pragma unroll
    for (int o = 16; o; o >>= 1) {
        p0 += __shfl_xor_sync(0xFFFFFFFFu, p0, o);
        p1 += __shfl_xor_sync(0xFFFFFFFFu, p1, o);
    }
    __syncthreads();   // red arrays reused
    if (lane == 0) { redm[tid >> 5] = p0; redd[tid >> 5] = p1; }
    __syncthreads();
    if (tid < 4) {
        float l0 = redm[tid], l1 = redd[tid];
#pragma unroll
        for (int o = 2; o; o >>= 1) {
            l0 += __shfl_xor_sync(0xFu, l0, o);
            l1 += __shfl_xor_sync(0xFu, l1, o);
        }
        if (tid == 0) {
            l0 += bc[0]; l1 += bc[1];
            float mx = fmaxf(l0, l1);
            float z0 = l0 - mx, z1 = l1 - mx;
            float lse = logf(expf(z0) + expf(z1));
            cls_out[(size_t)node * 2 + 0] = z0 - lse;
            cls_out[(size_t)node * 2 + 1] = z1 - lse;
        }
    }
}

// ---------------- launch ---------------------------------------------------------
extern "C" void kernel_launch(void* const* d_in, const int* in_sizes, int n_in,
                              void* d_out, int out_size) {
    const float* x   = (const float*)d_in[0];
    const int*   ei  = (const int*)d_in[1];    // int32 OR int64 (device-probed)
    const float* W1  = (const float*)d_in[2];
    const float* a1s = (const float*)d_in[3];
    const float* a1d = (const float*)d_in[4];
    const float* b1  = (const float*)d_in[5];
    const float* W2  = (const float*)d_in[6];
    const float* a2s = (const float*)d_in[7];
    const float* a2d = (const float*)d_in[8];
    const float* b2  = (const float*)d_in[9];
    const float* Wc  = (const float*)d_in[10];
    const float* bc  = (const float*)d_in[11];
    float*       out = (float*)d_out;

    dim3 ggrid((NN + 127) / 128, DD / 128);   // 391 x 2

    // Ordered so k_gemm is the 4th launch (ncu's profiled slot).
    // gemm1 depends only on x/W1/zeroed es-ed; CSR build is independent.
    k_detect<<<1, 1>>>(ei);
    k_init_deg<<<SCB, 256>>>();
    k_zero_attn<<<SCB, 256>>>();
    k_gemm<<<ggrid, 256>>>(x, W1, NN, a1s, a1d);          // 4th launch <- profiled

    // CSR build
    k_hist<<<(EE + 255) / 256, 256>>>(ei);
    k_scan1<<<SCB, 256>>>();
    k_scan2<<<1, 256>>>();
    k_scan3<<<SCB, 256>>>();
    k_fill<<<(ETOT + 255) / 256, 256>>>(ei);

    // layer 1 aggregation
    k_aggr<<<NN, 128>>>(b1, nullptr, nullptr, nullptr);

    // layer 2 (+ fused classifier)
    k_zero_attn<<<SCB, 256>>>();
    k_gemm<<<ggrid, 256>>>(nullptr, W2, NN, a2s, a2d);
    k_aggr<<<NN, 128>>>(b2, Wc, bc, out);
}

// round 17
// speedup vs baseline: 1.3814x; 1.0001x over previous
#include <cuda_runtime.h>
#include <cuda_fp16.h>
#include <math.h>
#include <stdint.h>

// Problem constants (fixed shapes per reference)
#define NN 50000
#define EE 800000
#define DD 256
#define CC 2
#define ETOT (EE + NN)   // edges + self loops = 850000
#define SLOPE 0.2f
#define SCB 196          // ceil(NN / 256) scan blocks

// ---------------- scratch (__device__ globals; device-code-only references) --
__device__ __half g_hA[(size_t)NN * DD];  // GEMM output h, fp16 (gather path only)
__device__ float  g_hB[(size_t)NN * DD];  // aggregated/relu'd layer output (fp32)
__device__ float  g_es[NN];
__device__ float  g_ed[NN];
__device__ int    g_deg[NN];
__device__ int    g_off[NN + 1];
__device__ int    g_cursor[NN];
__device__ int    g_csr_src[ETOT];
__device__ float  g_ex[ETOT];
__device__ int    g_part[256];            // scan partials (SCB used)
__device__ int    g_is64;                 // edge_index dtype flag

// ---------------- edge dtype probe ------------------------------------------
__global__ void k_detect(const int* __restrict__ ei) {
    int all0 = 1;
#pragma unroll
    for (int i = 1; i < 128; i += 2) all0 &= (ei[i] == 0);
    g_is64 = all0;
}

__device__ __forceinline__ int edge_src(const int* __restrict__ ei, int i) {
    return g_is64 ? ei[2 * i] : ei[i];
}
__device__ __forceinline__ int edge_dst(const int* __restrict__ ei, int i) {
    return g_is64 ? ei[2 * EE + 2 * i] : ei[EE + i];
}

// ---------------- CSR build ---------------------------------------------------
__global__ void k_init_deg() {
    int i = blockIdx.x * blockDim.x + threadIdx.x;
    if (i < NN) g_deg[i] = 1;   // self loop
}

__global__ void k_zero_attn() {
    int i = blockIdx.x * blockDim.x + threadIdx.x;
    if (i < NN) { g_es[i] = 0.f; g_ed[i] = 0.f; }
}

__global__ void k_hist(const int* __restrict__ ei) {
    int i = blockIdx.x * blockDim.x + threadIdx.x;
    if (i < EE) {
        int d = edge_dst(ei, i);
        if ((unsigned)d < NN) atomicAdd(&g_deg[d], 1);
    }
}

__global__ void k_scan1() {
    __shared__ int red[8];
    int i = blockIdx.x * 256 + threadIdx.x;
    int v = (i < NN) ? g_deg[i] : 0;
    int s = v;
#pragma unroll
    for (int o = 16; o; o >>= 1) s += __shfl_xor_sync(0xFFFFFFFFu, s, o);
    if ((threadIdx.x & 31) == 0) red[threadIdx.x >> 5] = s;
    __syncthreads();
    if (threadIdx.x < 8) {
        int t = red[threadIdx.x];
#pragma unroll
        for (int o = 4; o; o >>= 1) t += __shfl_xor_sync(0xFFu, t, o);
        if (threadIdx.x == 0) g_part[blockIdx.x] = t;
    }
}

__global__ void k_scan2() {
    __shared__ int sm[256];
    int t = threadIdx.x;
    int v = (t < SCB) ? g_part[t] : 0;
    sm[t] = v;
    __syncthreads();
#pragma unroll
    for (int off = 1; off < 256; off <<= 1) {
        int u = (t >= off) ? sm[t - off] : 0;
        __syncthreads();
        sm[t] += u;
        __syncthreads();
    }
    if (t < SCB) g_part[t] = sm[t] - v;
}

__global__ void k_scan3() {
    __shared__ int sm[256];
    int t = threadIdx.x;
    int i = blockIdx.x * 256 + t;
    int v = (i < NN) ? g_deg[i] : 0;
    sm[t] = v;
    __syncthreads();
#pragma unroll
    for (int off = 1; off < 256; off <<= 1) {
        int u = (t >= off) ? sm[t - off] : 0;
        __syncthreads();
        sm[t] += u;
        __syncthreads();
    }
    int excl = sm[t] - v + g_part[blockIdx.x];
    if (i < NN) { g_off[i] = excl; g_cursor[i] = excl; }
    if (i == NN - 1) g_off[NN] = excl + v;
}

__global__ void k_fill(const int* __restrict__ ei) {
    int i = blockIdx.x * blockDim.x + threadIdx.x;
    if (i >= ETOT) return;
    int s, d;
    if (i < EE) {
        s = edge_src(ei, i);
        d = edge_dst(ei, i);
        if ((unsigned)s >= NN || (unsigned)d >= NN) return;
    } else {
        s = d = i - EE;
    }
    int pos = atomicAdd(&g_cursor[d], 1);
    if ((unsigned)pos < ETOT) g_csr_src[pos] = s;
}

// ---------------- fp16 split helpers -------------------------------------------
__device__ __forceinline__ void fsplit(float x, __half& h, __half& l) {
    h = __float2half_rn(x);
    l = __float2half_rn(x - __half2float(h));
}

__device__ __forceinline__ void mma16816(float* c, const uint32_t* a, const uint32_t* b) {
    asm volatile(
        "mma.sync.aligned.m16n8k16.row.col.f32.f16.f16.f32 "
        "{%0,%1,%2,%3}, {%4,%5,%6,%7}, {%8,%9}, {%0,%1,%2,%3};\n"
        : "+f"(c[0]), "+f"(c[1]), "+f"(c[2]), "+f"(c[3])
        : "r"(a[0]), "r"(a[1]), "r"(a[2]), "r"(a[3]), "r"(b[0]), "r"(b[1]));
}

// ---------------- split-fp16 GEMM (3-term) + fused attention dots ---------------
// g_hA(fp16) = A @ W ; g_es += h.a_s ; g_ed += h.a_d    (dots at fp32)
// 128x128 CTA tile, BK=16, 8 warps (2m x 4n), warp tile 64x32, mma.m16n8k16.
// A smem [m][k] (24-half stride); B smem transposed [n][k] (26-half stride).
__global__ void __launch_bounds__(256)
k_gemm(const float* Aext, const float* __restrict__ B, int M,
       const float* __restrict__ a_s, const float* __restrict__ a_d) {
    const float* A = Aext ? Aext : (const float*)g_hB;
    __half* Cout = g_hA;
    const int K = 256, NC = 256;

    __shared__ __half Ash[128][24], Asl[128][24];   // [m][k]
    __shared__ __half Bsh[128][26], Bsl[128][26];   // [n][k]

    const int tid  = threadIdx.x;
    const int wid  = tid >> 5;
    const int lane = tid & 31;
    const int gid  = lane >> 2;      // 0..7
    const int tig  = lane & 3;       // 0..3
    const int wm   = wid >> 2;       // 0..1
    const int wn   = wid & 3;        // 0..3
    const int brow = blockIdx.x * 128;
    const int bcol = blockIdx.y * 128;

    // A global->smem mapping: thread = (1 row, 8 k)
    const int a_row = tid >> 1;          // 0..127
    const int a_k   = (tid & 1) * 8;     // 0 or 8
    const int gr    = brow + a_row;
    // B global->smem mapping: thread = (2 consecutive k rows, 4 n)
    const int b_kp  = tid >> 5;          // 0..7  (k pair index; k = 2*b_kp)
    const int b_n   = (tid & 31) * 4;    // 0..124 local n

    float acc[4][4][4];
#pragma unroll
    for (int mf = 0; mf < 4; mf++)
#pragma unroll
        for (int nf = 0; nf < 4; nf++)
#pragma unroll
            for (int c = 0; c < 4; c++) acc[mf][nf][c] = 0.f;

    float sa[8], sb0[4], sb1[4];

    // prologue: load + split + store tile k0=0
    {
        float4 av0 = make_float4(0.f, 0.f, 0.f, 0.f), av1 = av0;
        if (gr < M) {
            av0 = *(const float4*)&A[(size_t)gr * K + a_k];
            av1 = *(const float4*)&A[(size_t)gr * K + a_k + 4];
        }
        sa[0]=av0.x; sa[1]=av0.y; sa[2]=av0.z; sa[3]=av0.w;
        sa[4]=av1.x; sa[5]=av1.y; sa[6]=av1.z; sa[7]=av1.w;
        float4 bv0 = *(const float4*)&B[(size_t)(2 * b_kp) * NC + bcol + b_n];
        float4 bv1 = *(const float4*)&B[(size_t)(2 * b_kp + 1) * NC + bcol + b_n];
        sb0[0]=bv0.x; sb0[1]=bv0.y; sb0[2]=bv0.z; sb0[3]=bv0.w;
        sb1[0]=bv1.x; sb1[1]=bv1.y; sb1[2]=bv1.z; sb1[3]=bv1.w;
#pragma unroll
        for (int i = 0; i < 8; i++) {
            __half h, l;
            fsplit(sa[i], h, l);
            Ash[a_row][a_k + i] = h;
            Asl[a_row][a_k + i] = l;
        }
#pragma unroll
        for (int i = 0; i < 4; i++) {
            __half h0, l0, h1, l1;
            fsplit(sb0[i], h0, l0);
            fsplit(sb1[i], h1, l1);
            *(half2*)&Bsh[b_n + i][2 * b_kp] = __halves2half2(h0, h1);
            *(half2*)&Bsl[b_n + i][2 * b_kp] = __halves2half2(l0, l1);
        }
    }
    __syncthreads();

    for (int k0 = 16; k0 <= K; k0 += 16) {
        const bool more = (k0 < K);
        if (more) {   // prefetch next tile into registers (hidden by 48 MMAs/warp)
            float4 av0 = make_float4(0.f, 0.f, 0.f, 0.f), av1 = av0;
            if (gr < M) {
                av0 = *(const float4*)&A[(size_t)gr * K + k0 + a_k];
                av1 = *(const float4*)&A[(size_t)gr * K + k0 + a_k + 4];
            }
            sa[0]=av0.x; sa[1]=av0.y; sa[2]=av0.z; sa[3]=av0.w;
            sa[4]=av1.x; sa[5]=av1.y; sa[6]=av1.z; sa[7]=av1.w;
            float4 bv0 = *(const float4*)&B[(size_t)(k0 + 2 * b_kp) * NC + bcol + b_n];
            float4 bv1 = *(const float4*)&B[(size_t)(k0 + 2 * b_kp + 1) * NC + bcol + b_n];
            sb0[0]=bv0.x; sb0[1]=bv0.y; sb0[2]=bv0.z; sb0[3]=bv0.w;
            sb1[0]=bv1.x; sb1[1]=bv1.y; sb1[2]=bv1.z; sb1[3]=bv1.w;
        }

        // fragment loads (m16n8k16 layout)
        uint32_t ah[4][4], al[4][4], bh[4][2], bl[4][2];
#pragma unroll
        for (int mf = 0; mf < 4; mf++) {
            int m0 = wm * 64 + mf * 16 + gid;
            ah[mf][0] = *(const uint32_t*)&Ash[m0][2 * tig];
            ah[mf][1] = *(const uint32_t*)&Ash[m0 + 8][2 * tig];
            ah[mf][2] = *(const uint32_t*)&Ash[m0][2 * tig + 8];
            ah[mf][3] = *(const uint32_t*)&Ash[m0 + 8][2 * tig + 8];
            al[mf][0] = *(const uint32_t*)&Asl[m0][2 * tig];
            al[mf][1] = *(const uint32_t*)&Asl[m0 + 8][2 * tig];
            al[mf][2] = *(const uint32_t*)&Asl[m0][2 * tig + 8];
            al[mf][3] = *(const uint32_t*)&Asl[m0 + 8][2 * tig + 8];
        }
#pragma unroll
        for (int nf = 0; nf < 4; nf++) {
            int n0 = wn * 32 + nf * 8 + gid;
            bh[nf][0] = *(const uint32_t*)&Bsh[n0][2 * tig];
            bh[nf][1] = *(const uint32_t*)&Bsh[n0][2 * tig + 8];
            bl[nf][0] = *(const uint32_t*)&Bsl[n0][2 * tig];
            bl[nf][1] = *(const uint32_t*)&Bsl[n0][2 * tig + 8];
        }

        // 3-term split-fp16: D += Ah*Bh + Ah*Bl + Al*Bh
#pragma unroll
        for (int mf = 0; mf < 4; mf++)
#pragma unroll
            for (int nf = 0; nf < 4; nf++) {
                mma16816(acc[mf][nf], ah[mf], bh[nf]);
                mma16816(acc[mf][nf], ah[mf], bl[nf]);
                mma16816(acc[mf][nf], al[mf], bh[nf]);
            }

        if (more) {
            __syncthreads();   // fragment reads of current tile done
#pragma unroll
            for (int i = 0; i < 8; i++) {
                __half h, l;
                fsplit(sa[i], h, l);
                Ash[a_row][a_k + i] = h;
                Asl[a_row][a_k + i] = l;
            }
#pragma unroll
            for (int i = 0; i < 4; i++) {
                __half h0, l0, h1, l1;
                fsplit(sb0[i], h0, l0);
                fsplit(sb1[i], h1, l1);
                *(half2*)&Bsh[b_n + i][2 * b_kp] = __halves2half2(h0, h1);
                *(half2*)&Bsl[b_n + i][2 * b_kp] = __halves2half2(l0, l1);
            }
            __syncthreads();
        }
    }

    // epilogue: fused attention dots (fp32) + fp16 C store (layout unchanged)
    float as0[4], as1[4], ad0[4], ad1[4];
#pragma unroll
    for (int nf = 0; nf < 4; nf++) {
        int c = bcol + wn * 32 + nf * 8 + 2 * tig;
        as0[nf] = a_s[c];     as1[nf] = a_s[c + 1];
        ad0[nf] = a_d[c];     ad1[nf] = a_d[c + 1];
    }
#pragma unroll
    for (int mf = 0; mf < 4; mf++) {
        int r0 = brow + wm * 64 + mf * 16 + gid;
        int r1 = r0 + 8;
        float ps0 = 0.f, pd0 = 0.f, ps1 = 0.f, pd1 = 0.f;
#pragma unroll
        for (int nf = 0; nf < 4; nf++) {
            ps0 = fmaf(acc[mf][nf][0], as0[nf], fmaf(acc[mf][nf][1], as1[nf], ps0));
            pd0 = fmaf(acc[mf][nf][0], ad0[nf], fmaf(acc[mf][nf][1], ad1[nf], pd0));
            ps1 = fmaf(acc[mf][nf][2], as0[nf], fmaf(acc[mf][nf][3], as1[nf], ps1));
            pd1 = fmaf(acc[mf][nf][2], ad0[nf], fmaf(acc[mf][nf][3], ad1[nf], pd1));
        }
#pragma unroll
        for (int o = 1; o <= 2; o <<= 1) {
            ps0 += __shfl_xor_sync(0xFFFFFFFFu, ps0, o);
            pd0 += __shfl_xor_sync(0xFFFFFFFFu, pd0, o);
            ps1 += __shfl_xor_sync(0xFFFFFFFFu, ps1, o);
            pd1 += __shfl_xor_sync(0xFFFFFFFFu, pd1, o);
        }
#pragma unroll
        for (int nf = 0; nf < 4; nf++) {
            int c = bcol + wn * 32 + nf * 8 + 2 * tig;
            if (r0 < M)
                ((__half2*)Cout)[((size_t)r0 * NC + c) >> 1] =
                    __floats2half2_rn(acc[mf][nf][0], acc[mf][nf][1]);
            if (r1 < M)
                ((__half2*)Cout)[((size_t)r1 * NC + c) >> 1] =
                    __floats2half2_rn(acc[mf][nf][2], acc[mf][nf][3]);
        }
        if (tig == 0) {
            if (r0 < M) { atomicAdd(&g_es[r0], ps0); atomicAdd(&g_ed[r0], pd0); }
            if (r1 < M) { atomicAdd(&g_es[r1], ps1); atomicAdd(&g_ed[r1], pd1); }
        }
    }
}

// ---------------- aggregation: online segment softmax + fp16 gather -------------
// 128 threads per block; thread t owns the half2 feature pair (2t, 2t+1).
// If Wc != nullptr: fused classifier + log_softmax.
__global__ void __launch_bounds__(128)
k_aggr(const float* __restrict__ bias,
       const float* __restrict__ Wc, const float* __restrict__ bc,
       float* __restrict__ cls_out) {
    const __half2* Hin = (const __half2*)g_hA;
    const int node = blockIdx.x;
    const int tid = threadIdx.x;      // 0..127
    const int lane = tid & 31;
    const int beg = g_off[node];
    const int end = g_off[node + 1];
    const float edv = g_ed[node];

    __shared__ float redm[4], redd[4];
    __shared__ float s_m, s_inv;
    __shared__ int   s_src[128];
    __shared__ float s_w[128];

    // pass A: online softmax (max + denominator in one sweep); store raw e
    float m = -1e30f, d = 0.f;
    for (int j = beg + tid; j < end; j += 128) {
        float e = g_es[g_csr_src[j]] + edv;
        e = (e > 0.f) ? e : SLOPE * e;
        g_ex[j] = e;
        if (e > m) { d = fmaf(d, __expf(m - e), 1.f); m = e; }
        else       { d += __expf(e - m); }
    }
#pragma unroll
    for (int o = 16; o; o >>= 1) {
        float om = __shfl_xor_sync(0xFFFFFFFFu, m, o);
        float od = __shfl_xor_sync(0xFFFFFFFFu, d, o);
        float nm = fmaxf(m, om);
        d = d * __expf(m - nm) + od * __expf(om - nm);
        m = nm;
    }
    if (lane == 0) { redm[tid >> 5] = m; redd[tid >> 5] = d; }
    __syncthreads();
    if (tid < 4) {
        float vm = redm[tid], vd = redd[tid];
#pragma unroll
        for (int o = 2; o; o >>= 1) {
            float om = __shfl_xor_sync(0xFu, vm, o);
            float od = __shfl_xor_sync(0xFu, vd, o);
            float nm = fmaxf(vm, om);
            vd = vd * __expf(vm - nm) + od * __expf(om - nm);
            vm = nm;
        }
        if (tid == 0) { s_m = vm; s_inv = 1.f / vd; }
    }
    __syncthreads();
    const float mm  = s_m;
    const float inv = s_inv;

    // pass C: weighted fp16 gather (thread = one half2 feature pair)
    float ax = 0.f, ay = 0.f;
    for (int base = beg; base < end; base += 128) {
        int n = min(128, end - base);
        __syncthreads();
        if (tid < n) {
            s_src[tid] = g_csr_src[base + tid];
            s_w[tid]   = __expf(g_ex[base + tid] - mm);
        }
        __syncthreads();
        for (int k = 0; k < n; k++) {
            float w = s_w[k];
            float2 f = __half22float2(Hin[(size_t)s_src[k] * 128 + tid]);
            ax = fmaf(w, f.x, ax);
            ay = fmaf(w, f.y, ay);
        }
    }
    float v0 = fmaxf(fmaf(ax, inv, bias[2 * tid]), 0.f);
    float v1 = fmaxf(fmaf(ay, inv, bias[2 * tid + 1]), 0.f);

    if (Wc == nullptr) {
        ((float2*)g_hB)[(size_t)node * 128 + tid] = make_float2(v0, v1);
        return;
    }

    // fused classifier + log_softmax (Wc is [256,2] row-major)
    float p0 = v0 * Wc[4 * tid + 0] + v1 * Wc[4 * tid + 2];
    float p1 = v0 * Wc[4 * tid + 1] + v1 * Wc[4 * tid + 3];
#pragma unroll
    for (int o = 16; o; o >>= 1) {
        p0 += __shfl_xor_sync(0xFFFFFFFFu, p0, o);
        p1 += __shfl_xor_sync(0xFFFFFFFFu, p1, o);
    }
    __syncthreads();   // red arrays reused
    if (lane == 0) { redm[tid >> 5] = p0; redd[tid >> 5] = p1; }
    __syncthreads();
    if (tid < 4) {
        float l0 = redm[tid], l1 = redd[tid];
#pragma unroll
        for (int o = 2; o; o >>= 1) {
            l0 += __shfl_xor_sync(0xFu, l0, o);
            l1 += __shfl_xor_sync(0xFu, l1, o);
        }
        if (tid == 0) {
            l0 += bc[0]; l1 += bc[1];
            float mx = fmaxf(l0, l1);
            float z0 = l0 - mx, z1 = l1 - mx;
            float lse = logf(expf(z0) + expf(z1));
            cls_out[(size_t)node * 2 + 0] = z0 - lse;
            cls_out[(size_t)node * 2 + 1] = z1 - lse;
        }
    }
}

// ---------------- launch ---------------------------------------------------------
extern "C" void kernel_launch(void* const* d_in, const int* in_sizes, int n_in,
                              void* d_out, int out_size) {
    const float* x   = (const float*)d_in[0];
    const int*   ei  = (const int*)d_in[1];    // int32 OR int64 (device-probed)
    const float* W1  = (const float*)d_in[2];
    const float* a1s = (const float*)d_in[3];
    const float* a1d = (const float*)d_in[4];
    const float* b1  = (const float*)d_in[5];
    const float* W2  = (const float*)d_in[6];
    const float* a2s = (const float*)d_in[7];
    const float* a2d = (const float*)d_in[8];
    const float* b2  = (const float*)d_in[9];
    const float* Wc  = (const float*)d_in[10];
    const float* bc  = (const float*)d_in[11];
    float*       out = (float*)d_out;

    dim3 ggrid((NN + 127) / 128, DD / 128);   // 391 x 2

    // Ordered so k_gemm is the 4th launch (ncu's profiled slot).
    // gemm1 depends only on x/W1/zeroed es-ed; CSR build is independent.
    k_detect<<<1, 1>>>(ei);
    k_init_deg<<<SCB, 256>>>();
    k_zero_attn<<<SCB, 256>>>();
    k_gemm<<<ggrid, 256>>>(x, W1, NN, a1s, a1d);          // 4th launch <- profiled

    // CSR build
    k_hist<<<(EE + 255) / 256, 256>>>(ei);
    k_scan1<<<SCB, 256>>>();
    k_scan2<<<1, 256>>>();
    k_scan3<<<SCB, 256>>>();
    k_fill<<<(ETOT + 255) / 256, 256>>>(ei);

    // layer 1 aggregation
    k_aggr<<<NN, 128>>>(b1, nullptr, nullptr, nullptr);

    // layer 2 (+ fused classifier)
    k_zero_attn<<<SCB, 256>>>();
    k_gemm<<<ggrid, 256>>>(nullptr, W2, NN, a2s, a2d);
    k_aggr<<<NN, 128>>>(b2, Wc, bc, out);
}